// round 6
// baseline (speedup 1.0000x reference)
#include <cuda_runtime.h>
#include <math.h>

#define B_ 128
#define T_ 1024
#define D_ 128
#define U_ 256
#define M_ 64

// Static device scratch (no cudaMalloc anywhere)
__device__ float g_Cmem[U_ * U_];     // 0.1 * U_mem @ W_mem  [256][256]
__device__ float g_X[134217728];      // [t][gu(1024)][b(128)] fp32

// ---------------------------------------------------------------------------
// f32x2 packed helpers (FFMA2 — only reachable via PTX fma.rn.f32x2)
// ---------------------------------------------------------------------------
__device__ __forceinline__ void fma2(unsigned long long& d,
                                     unsigned long long a,
                                     unsigned long long b) {
    asm("fma.rn.f32x2 %0, %1, %2, %0;" : "+l"(d) : "l"(a), "l"(b));
}
__device__ __forceinline__ float sum2(unsigned long long v) {
    return __uint_as_float((unsigned)v) + __uint_as_float((unsigned)(v >> 32));
}
__device__ __forceinline__ unsigned long long pk2(float a, float b) {
    unsigned long long r;
    asm("mov.b64 %0, {%1, %2};" : "=l"(r) : "f"(a), "f"(b));
    return r;
}
__device__ __forceinline__ unsigned smu32(const void* p) {
    return (unsigned)__cvta_generic_to_shared(p);
}

// ---------------------------------------------------------------------------
// K0: Cmem[k][j] = 0.1 * sum_m U_mem[k][m] * W_mem[m][j]
// ---------------------------------------------------------------------------
__global__ void cmem_kernel(const float* __restrict__ Umem,
                            const float* __restrict__ Wmem) {
    int k = blockIdx.x, j = threadIdx.x;
    float s = 0.f;
#pragma unroll
    for (int m = 0; m < M_; m++)
        s += Umem[k * M_ + m] * Wmem[m * U_ + j];
    g_Cmem[k * U_ + j] = 0.1f * s;
}

// ---------------------------------------------------------------------------
// K1: input projections, f32x2. Tile 64 gu x 128 b, K=128. 256 thr, 4x8 micro.
// ---------------------------------------------------------------------------
#define K1_SMEM_BYTES ((128 * 68 + 128 * 130) * 4)
__global__ void __launch_bounds__(256) proj_kernel(
    const float* __restrict__ inp,
    const float* __restrict__ Wi, const float* __restrict__ Wf,
    const float* __restrict__ Wc, const float* __restrict__ Wo,
    const float* __restrict__ bi, const float* __restrict__ bf,
    const float* __restrict__ bc, const float* __restrict__ bo)
{
    extern __shared__ float sm[];
    float* Wsh = sm;               // [d=128][68]
    float* Ish = sm + 128 * 68;    // [b=128][130]

    const int t   = blockIdx.y;
    const int gu0 = blockIdx.x * 64;
    const int tid = threadIdx.x;

    const int g = gu0 >> 8;
    const float* Wg = (g == 0) ? Wi : (g == 1) ? Wf : (g == 2) ? Wc : Wo;
    const float* bv = (g == 0) ? bi : (g == 1) ? bf : (g == 2) ? bc : bo;
    const int u0 = gu0 & 255;

    for (int i = tid; i < 128 * 64; i += 256) {
        int d = i >> 6, j = i & 63;
        Wsh[d * 68 + j] = Wg[d * U_ + u0 + j];
    }
    for (int i = tid; i < 128 * 128; i += 256) {
        int b = i >> 7, d = i & 127;
        Ish[b * 130 + d] = inp[((size_t)b * T_ + t) * D_ + d];
    }
    __syncthreads();

    const int j4 = (tid & 15) * 4;
    const int b8 = (tid >> 4) * 8;

    unsigned long long acc[4][8];
#pragma unroll
    for (int jj = 0; jj < 4; jj++)
#pragma unroll
        for (int bb = 0; bb < 8; bb++) acc[jj][bb] = 0ull;

#pragma unroll 8
    for (int d = 0; d < 128; d += 2) {
        float4 wa = *(const float4*)&Wsh[d * 68 + j4];
        float4 wb = *(const float4*)&Wsh[(d + 1) * 68 + j4];
        unsigned long long w0 = pk2(wa.x, wb.x), w1 = pk2(wa.y, wb.y);
        unsigned long long w2 = pk2(wa.z, wb.z), w3 = pk2(wa.w, wb.w);
#pragma unroll
        for (int bb = 0; bb < 8; bb++) {
            unsigned long long iv =
                *(const unsigned long long*)&Ish[(b8 + bb) * 130 + d];
            fma2(acc[0][bb], w0, iv);
            fma2(acc[1][bb], w1, iv);
            fma2(acc[2][bb], w2, iv);
            fma2(acc[3][bb], w3, iv);
        }
    }

    float* outp = g_X + ((size_t)t * 1024 + gu0) * 128;
#pragma unroll
    for (int jj = 0; jj < 4; jj++) {
        float bb_ = bv[u0 + j4 + jj];
        float r[8];
#pragma unroll
        for (int bb = 0; bb < 8; bb++) r[bb] = sum2(acc[jj][bb]) + bb_;
        *(float4*)&outp[(size_t)(j4 + jj) * 128 + b8] =
            make_float4(r[0], r[1], r[2], r[3]);
        *(float4*)&outp[(size_t)(j4 + jj) * 128 + b8 + 4] =
            make_float4(r[4], r[5], r[6], r[7]);
    }
}

// ---------------------------------------------------------------------------
// K2: persistent recurrence, cluster-8, 640 threads.
// CTA (bg, sl): 8 batch rows x 32-col slice of {Ui,Uf,Uc,Uo,Cmem}.
// Thread map: g = tid>>7 (matrix), within-g warp w2 = kq_hi, lane: kq_lo, cp.
// Each thread: 2 cols x 32 K x 8 b = 256 FFMA2. shfl-reduce kq pairs in-warp.
// x_{t+1} register-prefetched at step start. c, r live in registers.
// h exchanged via DSMEM push + one barrier.cluster per step.
// ---------------------------------------------------------------------------
#define SMW_F4   10240                      // 5*8*8*2*16 float4 = 163840 B
#define SHH_OFF  (163840 / 4)               // [2][8][288] (+4 skew per 32)
#define SHH_STR  288
#define SHX_OFF  (SHH_OFF + 2 * 8 * 288)    // [4][32][9]
#define ZB_OFF   (SHX_OFF + 4 * 32 * 9)     // [4][5][256]
#define HST_OFF  (ZB_OFF + 4 * 5 * 256)     // [256]
#define R_SMEM_BYTES ((HST_OFF + 256) * 4)  // 208,384 B

__global__ void __launch_bounds__(640, 1) __cluster_dims__(8, 1, 1)
recur_kernel(const float* __restrict__ Ui, const float* __restrict__ Uf,
             const float* __restrict__ Uc, const float* __restrict__ Uo,
             float* __restrict__ out)
{
    extern __shared__ float sm[];
    float4* wsm4 = (float4*)sm;
    float*  shh  = sm + SHH_OFF;
    float*  shx  = sm + SHX_OFF;
    float*  zb   = sm + ZB_OFF;
    float*  hst  = sm + HST_OFF;

    const int bg  = blockIdx.x >> 3;
    const int sl  = blockIdx.x & 7;
    const int tid = threadIdx.x;
    const int g   = tid >> 7;               // 0..4  matrix
    const int w2  = (tid >> 5) & 3;         // kq_hi
    const int lane = tid & 31;
    const int kq8 = w2 * 2 + (lane >> 4);   // 0..7  K-eighth
    const int cp  = lane & 15;              // column pair

    // ---- weights into SMEM, f32x2-paired layout ----
    // float4 idx = (((g*8+kq8)*8 + j)*2 + p)*16 + lcp
    //   = { W[k][c0], W[k+1][c0], W[k][c1], W[k+1][c1] }, k = kq8*32+j*4+2p
    for (int idx = tid; idx < SMW_F4; idx += 640) {
        int lcp = idx & 15;
        int p   = (idx >> 4) & 1;
        int j   = (idx >> 5) & 7;
        int q8  = (idx >> 8) & 7;
        int gg  = idx >> 11;
        const float* W = (gg == 0) ? Ui : (gg == 1) ? Uf :
                         (gg == 2) ? Uc : (gg == 3) ? Uo : g_Cmem;
        int k   = q8 * 32 + j * 4 + 2 * p;
        int col = sl * 32 + lcp * 2;
        float4 v;
        v.x = W[(size_t)k * 256 + col];
        v.y = W[(size_t)(k + 1) * 256 + col];
        v.z = W[(size_t)k * 256 + col + 1];
        v.w = W[(size_t)(k + 1) * 256 + col + 1];
        wsm4[idx] = v;
    }
    for (int i = tid; i < 2 * 8 * SHH_STR; i += 640) shh[i] = 0.f;

    // gate-thread persistent quantities
    const int gb  = tid >> 5;               // batch row if tid<256
    const int gcc = tid & 31;               // col if tid<256
    const int u32_ = (tid >> 3) & 31;
    const int bb_  = tid & 7;
    size_t xoff = ((size_t)(sl * 32 + u32_)) * 128 + bg * 8 + bb_;
    float creg = 0.f, rreg = 0.f;

    if (tid < 256) {                        // stage x for t = 0
        const float* xp = g_X + xoff;
        shx[(0 * 32 + u32_) * 9 + bb_] = xp[0];
        shx[(1 * 32 + u32_) * 9 + bb_] = xp[32768];
        shx[(2 * 32 + u32_) * 9 + bb_] = xp[65536];
        shx[(3 * 32 + u32_) * 9 + bb_] = xp[98304];
    }
    __syncthreads();
    asm volatile("barrier.cluster.arrive.aligned;" ::: "memory");
    asm volatile("barrier.cluster.wait.aligned;" ::: "memory");

    const unsigned shh_u = smu32(shh);
    const float4*  wp    = wsm4 + (g * 8 + kq8) * 256 + cp;
    const int      kb0   = kq8 * 36;        // physical k base (skewed)

    for (int t = 0; t < T_; t++) {
        const int cur = t & 1, nxt = cur ^ 1;
        const float* hcur = shh + cur * (8 * SHH_STR);

        // ---- prefetch x_{t+1} into registers (hidden behind GEMV) ----
        float xr0, xr1, xr2, xr3;
        const bool pf = (tid < 256) && (t + 1 < T_);
        if (pf) {
            const float* xp = g_X + (size_t)(t + 1) * 131072 + xoff;
            xr0 = xp[0]; xr1 = xp[32768]; xr2 = xp[65536]; xr3 = xp[98304];
        }

        // ---- z = h_prev @ W : 2 cols, 32 K, 8 b per thread (f32x2) ----
        unsigned long long a0[8], a1[8];
#pragma unroll
        for (int b = 0; b < 8; b++) { a0[b] = 0ull; a1[b] = 0ull; }
#pragma unroll
        for (int j = 0; j < 8; j++) {
            ulonglong2 wa = *(const ulonglong2*)(wp + j * 32);
            ulonglong2 wb = *(const ulonglong2*)(wp + j * 32 + 16);
            const int kb = kb0 + j * 4;
#pragma unroll
            for (int b = 0; b < 8; b++) {
                ulonglong2 hh =
                    *(const ulonglong2*)(hcur + b * SHH_STR + kb);
                fma2(a0[b], wa.x, hh.x); fma2(a1[b], wa.y, hh.x);
                fma2(a0[b], wb.x, hh.y); fma2(a1[b], wb.y, hh.y);
            }
        }
        // in-warp reduce kq pairs (lanes L and L^16), store by low half
        {
            float s0[8], s1[8];
#pragma unroll
            for (int b = 0; b < 8; b++) {
                float v0 = sum2(a0[b]);
                v0 += __shfl_xor_sync(0xffffffffu, v0, 16);
                float v1 = sum2(a1[b]);
                v1 += __shfl_xor_sync(0xffffffffu, v1, 16);
                s0[b] = v0; s1[b] = v1;
            }
            if ((lane & 16) == 0) {
                float* z = zb + (w2 * 5 + g) * 256 + cp * 2;
#pragma unroll
                for (int b = 0; b < 8; b++) {
                    z[b * 32]     = s0[b];
                    z[b * 32 + 1] = s1[b];
                }
            }
        }
        __syncthreads();

        // ---- gates + state update (tid<256: one thread per (b, col)) ----
        if (tid < 256) {
            float zi = 0, zf = 0, zc = 0, zo = 0, zr = 0;
#pragma unroll
            for (int q = 0; q < 4; q++) {
                const float* zq = zb + q * 5 * 256 + gb * 32 + gcc;
                zi += zq[0];
                zf += zq[256];
                zc += zq[512];
                zo += zq[768];
                zr += zq[1024];
            }
            float rn = rreg + zr;
            float pi = shx[(0 * 32 + gcc) * 9 + gb] + zi + rn;
            float pf_ = shx[(1 * 32 + gcc) * 9 + gb] + zf;
            float pc = shx[(2 * 32 + gcc) * 9 + gb] + zc;
            float po = shx[(3 * 32 + gcc) * 9 + gb] + zo;
            float ig = __fdividef(1.f, 1.f + __expf(-pi));
            float fg = __fdividef(1.f, 1.f + __expf(-pf_));
            float ct = __fdividef(2.f, 1.f + __expf(-2.f * pc)) - 1.f;
            float og = __fdividef(1.f, 1.f + __expf(-po));
            float cn = fg * creg + ig * ct;
            float hv = og * (__fdividef(2.f, 1.f + __expf(-2.f * cn)) - 1.f);
            creg = cn;
            rreg = rn;
            hst[tid] = hv;
            out[((size_t)(bg * 8 + gb) * T_ + t) * U_ + sl * 32 + gcc] = hv;
        }
        __syncthreads();

        // ---- commit prefetched x (safe: gate reads done) ----
        if (pf) {
            shx[(0 * 32 + u32_) * 9 + bb_] = xr0;
            shx[(1 * 32 + u32_) * 9 + bb_] = xr1;
            shx[(2 * 32 + u32_) * 9 + bb_] = xr2;
            shx[(3 * 32 + u32_) * 9 + bb_] = xr3;
        }

        // ---- push h slice to all 8 CTAs' shh[nxt] via DSMEM ----
        if (tid < 512) {
            const int peer = tid >> 6, q = tid & 63;
            float4 v = ((const float4*)hst)[q];
            const int b  = q >> 3, c4 = (q & 7) * 4;
            unsigned dst = shh_u +
                (unsigned)((nxt * (8 * SHH_STR) + b * SHH_STR +
                            sl * 36 + c4) * 4);
            unsigned ra;
            asm("mapa.shared::cluster.u32 %0, %1, %2;"
                : "=r"(ra) : "r"(dst), "r"(peer));
            asm volatile(
                "st.shared::cluster.v4.b32 [%0], {%1,%2,%3,%4};"
                :: "r"(ra),
                   "r"(__float_as_uint(v.x)), "r"(__float_as_uint(v.y)),
                   "r"(__float_as_uint(v.z)), "r"(__float_as_uint(v.w))
                : "memory");
        }
        asm volatile("barrier.cluster.arrive.aligned;" ::: "memory");
        asm volatile("barrier.cluster.wait.aligned;" ::: "memory");
    }
}

// ---------------------------------------------------------------------------
// Launcher: capture-legal (kernel launches only, default stream)
// ---------------------------------------------------------------------------
extern "C" void kernel_launch(void* const* d_in, const int* in_sizes, int n_in,
                              void* d_out, int out_size)
{
    const float* inp  = (const float*)d_in[0];
    const float* Wi   = (const float*)d_in[1];
    const float* Wf   = (const float*)d_in[2];
    const float* Wc   = (const float*)d_in[3];
    const float* Wo   = (const float*)d_in[4];
    const float* Uig  = (const float*)d_in[5];
    const float* Ufg  = (const float*)d_in[6];
    const float* Ucg  = (const float*)d_in[7];
    const float* Uog  = (const float*)d_in[8];
    const float* Wmem = (const float*)d_in[9];
    const float* Umem = (const float*)d_in[10];
    const float* bi   = (const float*)d_in[11];
    const float* bf   = (const float*)d_in[12];
    const float* bc   = (const float*)d_in[13];
    const float* bo   = (const float*)d_in[14];
    float* out = (float*)d_out;

    cmem_kernel<<<256, 256, 0, 0>>>(Umem, Wmem);

    cudaFuncSetAttribute(proj_kernel,
                         cudaFuncAttributeMaxDynamicSharedMemorySize,
                         K1_SMEM_BYTES);
    dim3 pg(16, 1024);
    proj_kernel<<<pg, 256, K1_SMEM_BYTES, 0>>>(inp, Wi, Wf, Wc, Wo,
                                               bi, bf, bc, bo);

    cudaFuncSetAttribute(recur_kernel,
                         cudaFuncAttributeMaxDynamicSharedMemorySize,
                         R_SMEM_BYTES);
    recur_kernel<<<128, 640, R_SMEM_BYTES, 0>>>(Uig, Ufg, Ucg, Uog, out);
}

// round 7
// speedup vs baseline: 1.6398x; 1.6398x over previous
#include <cuda_runtime.h>
#include <math.h>

#define B_ 128
#define T_ 1024
#define D_ 128
#define U_ 256
#define M_ 64

// Static device scratch (no cudaMalloc anywhere)
__device__ float g_X[134217728];      // [t][gu(1024)][b(128)] fp32

// ---------------------------------------------------------------------------
// f32x2 packed helpers
// ---------------------------------------------------------------------------
__device__ __forceinline__ void fma2(unsigned long long& d,
                                     unsigned long long a,
                                     unsigned long long b) {
    asm("fma.rn.f32x2 %0, %1, %2, %0;" : "+l"(d) : "l"(a), "l"(b));
}
__device__ __forceinline__ float sum2(unsigned long long v) {
    return __uint_as_float((unsigned)v) + __uint_as_float((unsigned)(v >> 32));
}
__device__ __forceinline__ unsigned long long pk2(float a, float b) {
    unsigned long long r;
    asm("mov.b64 %0, {%1, %2};" : "=l"(r) : "f"(a), "f"(b));
    return r;
}
__device__ __forceinline__ unsigned smu32(const void* p) {
    return (unsigned)__cvta_generic_to_shared(p);
}

// ---------------------------------------------------------------------------
// K1: input projections, f32x2. Tile 64 gu x 128 b, K=128. 256 thr, 4x8 micro.
// ---------------------------------------------------------------------------
#define K1_SMEM_BYTES ((128 * 68 + 128 * 130) * 4)
__global__ void __launch_bounds__(256) proj_kernel(
    const float* __restrict__ inp,
    const float* __restrict__ Wi, const float* __restrict__ Wf,
    const float* __restrict__ Wc, const float* __restrict__ Wo,
    const float* __restrict__ bi, const float* __restrict__ bf,
    const float* __restrict__ bc, const float* __restrict__ bo)
{
    extern __shared__ float sm[];
    float* Wsh = sm;               // [d=128][68]
    float* Ish = sm + 128 * 68;    // [b=128][130]

    const int t   = blockIdx.y;
    const int gu0 = blockIdx.x * 64;
    const int tid = threadIdx.x;

    const int g = gu0 >> 8;
    const float* Wg = (g == 0) ? Wi : (g == 1) ? Wf : (g == 2) ? Wc : Wo;
    const float* bv = (g == 0) ? bi : (g == 1) ? bf : (g == 2) ? bc : bo;
    const int u0 = gu0 & 255;

    for (int i = tid; i < 128 * 64; i += 256) {
        int d = i >> 6, j = i & 63;
        Wsh[d * 68 + j] = Wg[d * U_ + u0 + j];
    }
    for (int i = tid; i < 128 * 128; i += 256) {
        int b = i >> 7, d = i & 127;
        Ish[b * 130 + d] = inp[((size_t)b * T_ + t) * D_ + d];
    }
    __syncthreads();

    const int j4 = (tid & 15) * 4;
    const int b8 = (tid >> 4) * 8;

    unsigned long long acc[4][8];
#pragma unroll
    for (int jj = 0; jj < 4; jj++)
#pragma unroll
        for (int bb = 0; bb < 8; bb++) acc[jj][bb] = 0ull;

#pragma unroll 8
    for (int d = 0; d < 128; d += 2) {
        float4 wa = *(const float4*)&Wsh[d * 68 + j4];
        float4 wb = *(const float4*)&Wsh[(d + 1) * 68 + j4];
        unsigned long long w0 = pk2(wa.x, wb.x), w1 = pk2(wa.y, wb.y);
        unsigned long long w2 = pk2(wa.z, wb.z), w3 = pk2(wa.w, wb.w);
#pragma unroll
        for (int bb = 0; bb < 8; bb++) {
            unsigned long long iv =
                *(const unsigned long long*)&Ish[(b8 + bb) * 130 + d];
            fma2(acc[0][bb], w0, iv);
            fma2(acc[1][bb], w1, iv);
            fma2(acc[2][bb], w2, iv);
            fma2(acc[3][bb], w3, iv);
        }
    }

    float* outp = g_X + ((size_t)t * 1024 + gu0) * 128;
#pragma unroll
    for (int jj = 0; jj < 4; jj++) {
        float bb_ = bv[u0 + j4 + jj];
        float r[8];
#pragma unroll
        for (int bb = 0; bb < 8; bb++) r[bb] = sum2(acc[jj][bb]) + bb_;
        *(float4*)&outp[(size_t)(j4 + jj) * 128 + b8] =
            make_float4(r[0], r[1], r[2], r[3]);
        *(float4*)&outp[(size_t)(j4 + jj) * 128 + b8 + 4] =
            make_float4(r[4], r[5], r[6], r[7]);
    }
}

// ---------------------------------------------------------------------------
// K2: persistent recurrence, cluster-8, 640 threads (20 warps, 5/SMSP).
// CTA (bg, sl): 8 batch rows x 32-col slice of {Ui,Uf,Uc,Uo,Cmem}.
// Cmem slice computed in prologue (fused; no separate kernel).
// Thread map: g = tid>>7 (matrix), kq8 = (tid>>4)&7 (K-eighth), cp = tid&15.
// Each thread: 2 cols x 32 K x 8 b = 256 fma2. No shfl: zbuf holds 8 partials.
// x_{t+1} register-prefetched; c, r in registers; 1 cluster barrier per step.
// ---------------------------------------------------------------------------
#define SMW_F4   10240                       // 5*8*8*2*16 float4 = 163840 B
#define SHH_OFF  (163840 / 4)                // [2][8][288]  (32->36 skew)
#define SHH_STR  288
#define SHX_OFF  (SHH_OFF + 2 * 8 * 288)     // [4][32][9]
#define ZB_OFF   (SHX_OFF + 4 * 32 * 9)      // [8][5][8][32]
#define HST_OFF  (ZB_OFF + 8 * 5 * 8 * 32)   // [256]
#define R_SMEM_BYTES ((HST_OFF + 256) * 4)   // 228,864 B

__global__ void __launch_bounds__(640, 1) __cluster_dims__(8, 1, 1)
recur_kernel(const float* __restrict__ Ui, const float* __restrict__ Uf,
             const float* __restrict__ Uc, const float* __restrict__ Uo,
             const float* __restrict__ Wmem, const float* __restrict__ Umem,
             float* __restrict__ out)
{
    extern __shared__ float sm[];
    float4* wsm4 = (float4*)sm;
    float*  shh  = sm + SHH_OFF;
    float*  shx  = sm + SHX_OFF;
    float*  zb   = sm + ZB_OFF;
    float*  hst  = sm + HST_OFF;

    const int bg   = blockIdx.x >> 3;
    const int sl   = blockIdx.x & 7;
    const int tid  = threadIdx.x;
    const int g    = tid >> 7;               // 0..4  matrix
    const int kq8  = (tid >> 4) & 7;         // 0..7  K-eighth
    const int cp   = tid & 15;               // column pair

    // ---- weights into SMEM, f32x2-paired layout ----
    // float4 idx = (gg*8+q8)*256 + j*32 + p*16 + lcp
    //   = { W[k][c0], W[k+1][c0], W[k][c1], W[k+1][c1] },  k = q8*32+j*4+2p
    // gg==4 (Cmem) is computed from Umem/Wmem on the fly.
    for (int idx = tid; idx < SMW_F4; idx += 640) {
        int lcp = idx & 15;
        int p   = (idx >> 4) & 1;
        int j   = (idx >> 5) & 7;
        int q8  = (idx >> 8) & 7;
        int gg  = idx >> 11;
        int k   = q8 * 32 + j * 4 + 2 * p;
        int col = sl * 32 + lcp * 2;
        float4 v;
        if (gg < 4) {
            const float* W = (gg == 0) ? Ui : (gg == 1) ? Uf :
                             (gg == 2) ? Uc : Uo;
            v.x = W[(size_t)k * 256 + col];
            v.y = W[(size_t)(k + 1) * 256 + col];
            v.z = W[(size_t)k * 256 + col + 1];
            v.w = W[(size_t)(k + 1) * 256 + col + 1];
        } else {
            float s00 = 0.f, s10 = 0.f, s01 = 0.f, s11 = 0.f;
#pragma unroll 8
            for (int m = 0; m < M_; m++) {
                float u0 = Umem[k * M_ + m];
                float u1 = Umem[(k + 1) * M_ + m];
                float w0 = Wmem[m * U_ + col];
                float w1 = Wmem[m * U_ + col + 1];
                s00 = fmaf(u0, w0, s00); s10 = fmaf(u1, w0, s10);
                s01 = fmaf(u0, w1, s01); s11 = fmaf(u1, w1, s11);
            }
            v.x = 0.1f * s00; v.y = 0.1f * s10;
            v.z = 0.1f * s01; v.w = 0.1f * s11;
        }
        wsm4[idx] = v;
    }
    for (int i = tid; i < 2 * 8 * SHH_STR; i += 640) shh[i] = 0.f;

    // gate-thread persistent quantities (tid < 256)
    const int gb   = tid >> 5;
    const int gcc  = tid & 31;
    const int u32_ = (tid >> 3) & 31;
    const int bb_  = tid & 7;
    size_t xoff = ((size_t)(sl * 32 + u32_)) * 128 + bg * 8 + bb_;
    float creg = 0.f, rreg = 0.f;

    if (tid < 256) {                        // stage x for t = 0
        const float* xp = g_X + xoff;
        shx[(0 * 32 + u32_) * 9 + bb_] = xp[0];
        shx[(1 * 32 + u32_) * 9 + bb_] = xp[32768];
        shx[(2 * 32 + u32_) * 9 + bb_] = xp[65536];
        shx[(3 * 32 + u32_) * 9 + bb_] = xp[98304];
    }
    __syncthreads();
    asm volatile("barrier.cluster.arrive.aligned;" ::: "memory");
    asm volatile("barrier.cluster.wait.aligned;" ::: "memory");

    const unsigned shh_u = smu32(shh);
    const float4*  wp    = wsm4 + (g * 8 + kq8) * 256 + cp;
    const int      kb0   = kq8 * 36;        // physical (skewed) k base
    float*         zrow  = zb + (kq8 * 5 + g) * 256 + cp * 2;

    for (int t = 0; t < T_; t++) {
        const int cur = t & 1, nxt = cur ^ 1;
        const float* hcur = shh + cur * (8 * SHH_STR);

        // ---- prefetch x_{t+1} into registers (hidden behind GEMV) ----
        float xr0, xr1, xr2, xr3;
        const bool pf = (tid < 256) && (t + 1 < T_);
        if (pf) {
            const float* xp = g_X + (size_t)(t + 1) * 131072 + xoff;
            xr0 = xp[0]; xr1 = xp[32768]; xr2 = xp[65536]; xr3 = xp[98304];
        }

        // ---- z = h_prev @ W : 2 cols, 32 K, 8 b per thread (f32x2) ----
        unsigned long long a0[8], a1[8];
#pragma unroll
        for (int b = 0; b < 8; b++) { a0[b] = 0ull; a1[b] = 0ull; }
#pragma unroll
        for (int j = 0; j < 8; j++) {
            ulonglong2 wa = *(const ulonglong2*)(wp + j * 32);
            ulonglong2 wb = *(const ulonglong2*)(wp + j * 32 + 16);
            const int kb = kb0 + j * 4;
#pragma unroll
            for (int b = 0; b < 8; b++) {
                ulonglong2 hh =
                    *(const ulonglong2*)(hcur + b * SHH_STR + kb);
                fma2(a0[b], wa.x, hh.x); fma2(a1[b], wa.y, hh.x);
                fma2(a0[b], wb.x, hh.y); fma2(a1[b], wb.y, hh.y);
            }
        }
#pragma unroll
        for (int b = 0; b < 8; b++) {
            float2 z2 = make_float2(sum2(a0[b]), sum2(a1[b]));
            *(float2*)(zrow + b * 32) = z2;
        }
        __syncthreads();

        // ---- gates + state update (tid<256: one thread per (b, col)) ----
        if (tid < 256) {
            float zi = 0, zf = 0, zc = 0, zo = 0, zr = 0;
#pragma unroll
            for (int q = 0; q < 8; q++) {
                const float* zq = zb + q * 5 * 256 + gb * 32 + gcc;
                zi += zq[0];
                zf += zq[256];
                zc += zq[512];
                zo += zq[768];
                zr += zq[1024];
            }
            float rn = rreg + zr;
            float pi  = shx[(0 * 32 + gcc) * 9 + gb] + zi + rn;
            float pff = shx[(1 * 32 + gcc) * 9 + gb] + zf;
            float pc  = shx[(2 * 32 + gcc) * 9 + gb] + zc;
            float po  = shx[(3 * 32 + gcc) * 9 + gb] + zo;
            float ig = __fdividef(1.f, 1.f + __expf(-pi));
            float fg = __fdividef(1.f, 1.f + __expf(-pff));
            float ct = __fdividef(2.f, 1.f + __expf(-2.f * pc)) - 1.f;
            float og = __fdividef(1.f, 1.f + __expf(-po));
            float cn = fg * creg + ig * ct;
            float hv = og * (__fdividef(2.f, 1.f + __expf(-2.f * cn)) - 1.f);
            creg = cn;
            rreg = rn;
            hst[tid] = hv;
            out[((size_t)(bg * 8 + gb) * T_ + t) * U_ + sl * 32 + gcc] = hv;
        }
        __syncthreads();

        // ---- commit prefetched x (gate reads of shx are done) ----
        if (pf) {
            shx[(0 * 32 + u32_) * 9 + bb_] = xr0;
            shx[(1 * 32 + u32_) * 9 + bb_] = xr1;
            shx[(2 * 32 + u32_) * 9 + bb_] = xr2;
            shx[(3 * 32 + u32_) * 9 + bb_] = xr3;
        }

        // ---- push h slice to all 8 CTAs' shh[nxt] via DSMEM ----
        if (tid < 512) {
            const int peer = tid >> 6, q = tid & 63;
            float4 v = ((const float4*)hst)[q];
            const int b  = q >> 3, c4 = (q & 7) * 4;
            unsigned dst = shh_u +
                (unsigned)((nxt * (8 * SHH_STR) + b * SHH_STR +
                            sl * 36 + c4) * 4);
            unsigned ra;
            asm("mapa.shared::cluster.u32 %0, %1, %2;"
                : "=r"(ra) : "r"(dst), "r"(peer));
            asm volatile(
                "st.shared::cluster.v4.b32 [%0], {%1,%2,%3,%4};"
                :: "r"(ra),
                   "r"(__float_as_uint(v.x)), "r"(__float_as_uint(v.y)),
                   "r"(__float_as_uint(v.z)), "r"(__float_as_uint(v.w))
                : "memory");
        }
        asm volatile("barrier.cluster.arrive.aligned;" ::: "memory");
        asm volatile("barrier.cluster.wait.aligned;" ::: "memory");
    }
}

// ---------------------------------------------------------------------------
// Launcher: capture-legal (exactly 2 kernel launches, default stream)
// ---------------------------------------------------------------------------
extern "C" void kernel_launch(void* const* d_in, const int* in_sizes, int n_in,
                              void* d_out, int out_size)
{
    const float* inp  = (const float*)d_in[0];
    const float* Wi   = (const float*)d_in[1];
    const float* Wf   = (const float*)d_in[2];
    const float* Wc   = (const float*)d_in[3];
    const float* Wo   = (const float*)d_in[4];
    const float* Uig  = (const float*)d_in[5];
    const float* Ufg  = (const float*)d_in[6];
    const float* Ucg  = (const float*)d_in[7];
    const float* Uog  = (const float*)d_in[8];
    const float* Wmem = (const float*)d_in[9];
    const float* Umem = (const float*)d_in[10];
    const float* bi   = (const float*)d_in[11];
    const float* bf   = (const float*)d_in[12];
    const float* bc   = (const float*)d_in[13];
    const float* bo   = (const float*)d_in[14];
    float* out = (float*)d_out;

    cudaFuncSetAttribute(proj_kernel,
                         cudaFuncAttributeMaxDynamicSharedMemorySize,
                         K1_SMEM_BYTES);
    dim3 pg(16, 1024);
    proj_kernel<<<pg, 256, K1_SMEM_BYTES, 0>>>(inp, Wi, Wf, Wc, Wo,
                                               bi, bf, bc, bo);

    cudaFuncSetAttribute(recur_kernel,
                         cudaFuncAttributeMaxDynamicSharedMemorySize,
                         R_SMEM_BYTES);
    recur_kernel<<<128, 640, R_SMEM_BYTES, 0>>>(Uig, Ufg, Ucg, Uog,
                                                Wmem, Umem, out);
}

// round 8
// speedup vs baseline: 1.8322x; 1.1173x over previous
#include <cuda_runtime.h>
#include <math.h>

#define B_ 128
#define T_ 1024
#define D_ 128
#define U_ 256
#define M_ 64

// Static device scratch (no cudaMalloc anywhere)
__device__ float g_X[134217728];      // [t][gu(1024)][b(128)] fp32

// ---------------------------------------------------------------------------
// f32x2 packed helpers
// ---------------------------------------------------------------------------
__device__ __forceinline__ void fma2(unsigned long long& d,
                                     unsigned long long a,
                                     unsigned long long b) {
    asm("fma.rn.f32x2 %0, %1, %2, %0;" : "+l"(d) : "l"(a), "l"(b));
}
__device__ __forceinline__ float sum2(unsigned long long v) {
    return __uint_as_float((unsigned)v) + __uint_as_float((unsigned)(v >> 32));
}
__device__ __forceinline__ unsigned long long pk2(float a, float b) {
    unsigned long long r;
    asm("mov.b64 %0, {%1, %2};" : "=l"(r) : "f"(a), "f"(b));
    return r;
}
__device__ __forceinline__ unsigned smu32(const void* p) {
    return (unsigned)__cvta_generic_to_shared(p);
}

// ---- mbarrier / st.async primitives ----
__device__ __forceinline__ void mb_init(unsigned mbar, unsigned count) {
    asm volatile("mbarrier.init.shared.b64 [%0], %1;"
                 :: "r"(mbar), "r"(count) : "memory");
}
__device__ __forceinline__ void mb_expect_tx(unsigned mbar, unsigned bytes) {
    asm volatile("mbarrier.arrive.expect_tx.shared.b64 _, [%0], %1;"
                 :: "r"(mbar), "r"(bytes) : "memory");
}
__device__ __forceinline__ void mb_wait(unsigned mbar, unsigned parity) {
    unsigned done;
    asm volatile(
        "{\n\t.reg .pred p;\n\t"
        "mbarrier.try_wait.parity.acquire.cta.shared::cta.b64 p, [%1], %2;\n\t"
        "selp.b32 %0, 1, 0, p;\n\t}"
        : "=r"(done) : "r"(mbar), "r"(parity) : "memory");
    while (!done) {
        asm volatile(
            "{\n\t.reg .pred p;\n\t"
            "mbarrier.try_wait.parity.acquire.cta.shared::cta.b64 p, [%1], %2, 0x989680;\n\t"
            "selp.b32 %0, 1, 0, p;\n\t}"
            : "=r"(done) : "r"(mbar), "r"(parity) : "memory");
    }
}
// Store 4B into peer CTA's smem; tx-counted at peer's co-located mbarrier.
__device__ __forceinline__ void push_async(unsigned dst_local,
                                           unsigned mbar_local,
                                           int peer, float v) {
    unsigned rd, rm;
    asm("mapa.shared::cluster.u32 %0, %1, %2;" : "=r"(rd)
        : "r"(dst_local), "r"(peer));
    asm("mapa.shared::cluster.u32 %0, %1, %2;" : "=r"(rm)
        : "r"(mbar_local), "r"(peer));
    asm volatile(
        "st.async.shared::cluster.mbarrier::complete_tx::bytes.b32 [%0], %1, [%2];"
        :: "r"(rd), "r"(__float_as_uint(v)), "r"(rm) : "memory");
}

// ---------------------------------------------------------------------------
// K1: input projections, f32x2. Tile 64 gu x 128 b, K=128. 256 thr, 4x8 micro.
// ---------------------------------------------------------------------------
#define K1_SMEM_BYTES ((128 * 68 + 128 * 130) * 4)
__global__ void __launch_bounds__(256) proj_kernel(
    const float* __restrict__ inp,
    const float* __restrict__ Wi, const float* __restrict__ Wf,
    const float* __restrict__ Wc, const float* __restrict__ Wo,
    const float* __restrict__ bi, const float* __restrict__ bf,
    const float* __restrict__ bc, const float* __restrict__ bo)
{
    extern __shared__ float sm[];
    float* Wsh = sm;               // [d=128][68]
    float* Ish = sm + 128 * 68;    // [b=128][130]

    const int t   = blockIdx.y;
    const int gu0 = blockIdx.x * 64;
    const int tid = threadIdx.x;

    const int g = gu0 >> 8;
    const float* Wg = (g == 0) ? Wi : (g == 1) ? Wf : (g == 2) ? Wc : Wo;
    const float* bv = (g == 0) ? bi : (g == 1) ? bf : (g == 2) ? bc : bo;
    const int u0 = gu0 & 255;

    for (int i = tid; i < 128 * 64; i += 256) {
        int d = i >> 6, j = i & 63;
        Wsh[d * 68 + j] = Wg[d * U_ + u0 + j];
    }
    for (int i = tid; i < 128 * 128; i += 256) {
        int b = i >> 7, d = i & 127;
        Ish[b * 130 + d] = inp[((size_t)b * T_ + t) * D_ + d];
    }
    __syncthreads();

    const int j4 = (tid & 15) * 4;
    const int b8 = (tid >> 4) * 8;

    unsigned long long acc[4][8];
#pragma unroll
    for (int jj = 0; jj < 4; jj++)
#pragma unroll
        for (int bb = 0; bb < 8; bb++) acc[jj][bb] = 0ull;

#pragma unroll 8
    for (int d = 0; d < 128; d += 2) {
        float4 wa = *(const float4*)&Wsh[d * 68 + j4];
        float4 wb = *(const float4*)&Wsh[(d + 1) * 68 + j4];
        unsigned long long w0 = pk2(wa.x, wb.x), w1 = pk2(wa.y, wb.y);
        unsigned long long w2 = pk2(wa.z, wb.z), w3 = pk2(wa.w, wb.w);
#pragma unroll
        for (int bb = 0; bb < 8; bb++) {
            unsigned long long iv =
                *(const unsigned long long*)&Ish[(b8 + bb) * 130 + d];
            fma2(acc[0][bb], w0, iv);
            fma2(acc[1][bb], w1, iv);
            fma2(acc[2][bb], w2, iv);
            fma2(acc[3][bb], w3, iv);
        }
    }

    float* outp = g_X + ((size_t)t * 1024 + gu0) * 128;
#pragma unroll
    for (int jj = 0; jj < 4; jj++) {
        float bb_ = bv[u0 + j4 + jj];
        float r[8];
#pragma unroll
        for (int bb = 0; bb < 8; bb++) r[bb] = sum2(acc[jj][bb]) + bb_;
        *(float4*)&outp[(size_t)(j4 + jj) * 128 + b8] =
            make_float4(r[0], r[1], r[2], r[3]);
        *(float4*)&outp[(size_t)(j4 + jj) * 128 + b8 + 4] =
            make_float4(r[4], r[5], r[6], r[7]);
    }
}

// ---------------------------------------------------------------------------
// K2: persistent recurrence, cluster-8, 640 threads, mbarrier dataflow.
// CTA (bg, sl): 8 batch rows x 32-col slice of {Ui,Uf,Uc,Uo,Cmem}.
// 8 mbarriers per CTA: mbar[q] guards the h K-slice produced by peer q.
// Gate threads st.async their h value into all 8 peers (tx-counted).
// GEMV thread waits only mbar[kq8] — fine-grained, skew pipelines.
// ---------------------------------------------------------------------------
#define SMW_F4   10240                       // 5*8*8*2*16 float4 = 163840 B
#define SHH_OFF  40960                       // [2][8][288]  (32->36 skew)
#define SHH_STR  288
#define SHX_OFF  (SHH_OFF + 2 * 8 * 288)     // [4][32][9]
#define ZB_OFF   (SHX_OFF + 4 * 32 * 9)      // [8][5][8][32]
#define MBAR_OFF (ZB_OFF + 8 * 5 * 8 * 32)   // 8 mbarriers (64 B)
#define R_SMEM_BYTES ((MBAR_OFF + 16) * 4)   // 227,904 B

__global__ void __launch_bounds__(640, 1) __cluster_dims__(8, 1, 1)
recur_kernel(const float* __restrict__ Ui, const float* __restrict__ Uf,
             const float* __restrict__ Uc, const float* __restrict__ Uo,
             const float* __restrict__ Wmem, const float* __restrict__ Umem,
             float* __restrict__ out)
{
    extern __shared__ float sm[];
    float4* wsm4 = (float4*)sm;
    float*  shh  = sm + SHH_OFF;
    float*  shx  = sm + SHX_OFF;
    float*  zb   = sm + ZB_OFF;

    const int bg   = blockIdx.x >> 3;
    const int sl   = blockIdx.x & 7;
    const int tid  = threadIdx.x;
    const int g    = tid >> 7;               // 0..4  matrix
    const int kq8  = (tid >> 4) & 7;         // 0..7  K-eighth
    const int cp   = tid & 15;               // column pair

    const unsigned smb    = smu32(sm);
    const unsigned shh_u  = smb + SHH_OFF * 4;
    const unsigned mb0    = smb + MBAR_OFF * 4;   // mbar[q] = mb0 + q*8
    const unsigned my_mb  = mb0 + (unsigned)kq8 * 8;

    // ---- mbarrier init (count=1: the per-phase expect_tx arrive) ----
    if (tid < 8) mb_init(mb0 + tid * 8, 1);
    __syncthreads();
    asm volatile("barrier.cluster.arrive.aligned;" ::: "memory");
    asm volatile("barrier.cluster.wait.aligned;" ::: "memory");

    // ---- weights into SMEM, f32x2-paired layout ----
    // float4 idx = (gg*8+q8)*256 + j*32 + p*16 + lcp
    //   = { W[k][c0], W[k+1][c0], W[k][c1], W[k+1][c1] },  k = q8*32+j*4+2p
    // gg==4 (Cmem = 0.1*Umem@Wmem) computed on the fly.
    for (int idx = tid; idx < SMW_F4; idx += 640) {
        int lcp = idx & 15;
        int p   = (idx >> 4) & 1;
        int j   = (idx >> 5) & 7;
        int q8  = (idx >> 8) & 7;
        int gg  = idx >> 11;
        int k   = q8 * 32 + j * 4 + 2 * p;
        int col = sl * 32 + lcp * 2;
        float4 v;
        if (gg < 4) {
            const float* W = (gg == 0) ? Ui : (gg == 1) ? Uf :
                             (gg == 2) ? Uc : Uo;
            v.x = W[(size_t)k * 256 + col];
            v.y = W[(size_t)(k + 1) * 256 + col];
            v.z = W[(size_t)k * 256 + col + 1];
            v.w = W[(size_t)(k + 1) * 256 + col + 1];
        } else {
            float s00 = 0.f, s10 = 0.f, s01 = 0.f, s11 = 0.f;
#pragma unroll 8
            for (int m = 0; m < M_; m++) {
                float u0 = Umem[k * M_ + m];
                float u1 = Umem[(k + 1) * M_ + m];
                float w0 = Wmem[m * U_ + col];
                float w1 = Wmem[m * U_ + col + 1];
                s00 = fmaf(u0, w0, s00); s10 = fmaf(u1, w0, s10);
                s01 = fmaf(u0, w1, s01); s11 = fmaf(u1, w1, s11);
            }
            v.x = 0.1f * s00; v.y = 0.1f * s10;
            v.z = 0.1f * s01; v.w = 0.1f * s11;
        }
        wsm4[idx] = v;
    }

    // gate-thread persistent quantities (tid < 256)
    const int gb   = tid >> 5;
    const int gcc  = tid & 31;
    const int u32_ = (tid >> 3) & 31;
    const int bb_  = tid & 7;
    size_t xoff = ((size_t)(sl * 32 + u32_)) * 128 + bg * 8 + bb_;
    float creg = 0.f, rreg = 0.f;

    // local-offset of this gate thread's h slot (within a buffer)
    const unsigned hslot = (unsigned)(gb * SHH_STR + sl * 36 + gcc) * 4;
    const unsigned own_mb = mb0 + (unsigned)sl * 8;

    if (tid < 256) {                        // stage x for t = 0
        const float* xp = g_X + xoff;
        shx[(0 * 32 + u32_) * 9 + bb_] = xp[0];
        shx[(1 * 32 + u32_) * 9 + bb_] = xp[32768];
        shx[(2 * 32 + u32_) * 9 + bb_] = xp[65536];
        shx[(3 * 32 + u32_) * 9 + bb_] = xp[98304];
    }
    // post expect for phase 0 (one thread per slice-mbarrier)
    if (g == 0 && cp == 0) mb_expect_tx(my_mb, 1024);
    __syncthreads();

    // h0 = 0: push zeros through the protocol into buffer 0 (phase 0)
    if (tid < 256) {
#pragma unroll
        for (int peer = 0; peer < 8; peer++)
            push_async(shh_u + hslot, own_mb, peer, 0.f);
    }

    const float4* wp  = wsm4 + (g * 8 + kq8) * 256 + cp;
    const int     kb0 = kq8 * 36;           // physical (skewed) k base
    float*        zrow = zb + (kq8 * 5 + g) * 256 + cp * 2;

    for (int t = 0; t < T_; t++) {
        const int cur = t & 1, nxt = cur ^ 1;
        const float* hcur = shh + cur * (8 * SHH_STR);

        // ---- prefetch x_{t+1} into registers (no h dependency) ----
        float xr0, xr1, xr2, xr3;
        const bool pf = (tid < 256) && (t + 1 < T_);
        if (pf) {
            const float* xp = g_X + (size_t)(t + 1) * 131072 + xoff;
            xr0 = xp[0]; xr1 = xp[32768]; xr2 = xp[65536]; xr3 = xp[98304];
        }

        // ---- wait for my K-slice of h, then repost expect for next phase --
        mb_wait(my_mb, (unsigned)(t & 1));
        if (g == 0 && cp == 0) mb_expect_tx(my_mb, 1024);

        // ---- z = h_prev @ W : 2 cols, 32 K, 8 b per thread (f32x2) ----
        unsigned long long a0[8], a1[8];
#pragma unroll
        for (int b = 0; b < 8; b++) { a0[b] = 0ull; a1[b] = 0ull; }
#pragma unroll
        for (int j = 0; j < 8; j++) {
            ulonglong2 wa = *(const ulonglong2*)(wp + j * 32);
            ulonglong2 wb = *(const ulonglong2*)(wp + j * 32 + 16);
            const int kb = kb0 + j * 4;
#pragma unroll
            for (int b = 0; b < 8; b++) {
                ulonglong2 hh =
                    *(const ulonglong2*)(hcur + b * SHH_STR + kb);
                fma2(a0[b], wa.x, hh.x); fma2(a1[b], wa.y, hh.x);
                fma2(a0[b], wb.x, hh.y); fma2(a1[b], wb.y, hh.y);
            }
        }
#pragma unroll
        for (int b = 0; b < 8; b++) {
            float2 z2 = make_float2(sum2(a0[b]), sum2(a1[b]));
            *(float2*)(zrow + b * 32) = z2;
        }
        __syncthreads();

        // ---- gates + state update + push (tid<256: one (b, col) cell) ----
        if (tid < 256) {
            float zi = 0, zf = 0, zc = 0, zo = 0, zr = 0;
#pragma unroll
            for (int q = 0; q < 8; q++) {
                const float* zq = zb + q * 5 * 256 + gb * 32 + gcc;
                zi += zq[0];
                zf += zq[256];
                zc += zq[512];
                zo += zq[768];
                zr += zq[1024];
            }
            float rn = rreg + zr;
            float pi  = shx[(0 * 32 + gcc) * 9 + gb] + zi + rn;
            float pff = shx[(1 * 32 + gcc) * 9 + gb] + zf;
            float pc  = shx[(2 * 32 + gcc) * 9 + gb] + zc;
            float po  = shx[(3 * 32 + gcc) * 9 + gb] + zo;
            float ig = __fdividef(1.f, 1.f + __expf(-pi));
            float fg = __fdividef(1.f, 1.f + __expf(-pff));
            float ct = __fdividef(2.f, 1.f + __expf(-2.f * pc)) - 1.f;
            float og = __fdividef(1.f, 1.f + __expf(-po));
            float cn = fg * creg + ig * ct;
            float hv = og * (__fdividef(2.f, 1.f + __expf(-2.f * cn)) - 1.f);
            creg = cn;
            rreg = rn;

            // push h_t into all 8 peers' buffer (t+1)&1 (tx-counted)
            if (t + 1 < T_) {
                unsigned dst = shh_u +
                    (unsigned)(nxt * (8 * SHH_STR) * 4) + hslot;
#pragma unroll
                for (int peer = 0; peer < 8; peer++)
                    push_async(dst, own_mb, peer, hv);
            }
            out[((size_t)(bg * 8 + gb) * T_ + t) * U_ + sl * 32 + gcc] = hv;
        }
        __syncthreads();

        // ---- commit prefetched x (all step-t shx reads done) ----
        if (pf) {
            shx[(0 * 32 + u32_) * 9 + bb_] = xr0;
            shx[(1 * 32 + u32_) * 9 + bb_] = xr1;
            shx[(2 * 32 + u32_) * 9 + bb_] = xr2;
            shx[(3 * 32 + u32_) * 9 + bb_] = xr3;
        }
    }

    // no CTA may exit while peers' st.async targeting its SMEM is in flight
    asm volatile("barrier.cluster.arrive.aligned;" ::: "memory");
    asm volatile("barrier.cluster.wait.aligned;" ::: "memory");
}

// ---------------------------------------------------------------------------
// Launcher: capture-legal (exactly 2 kernel launches, default stream)
// ---------------------------------------------------------------------------
extern "C" void kernel_launch(void* const* d_in, const int* in_sizes, int n_in,
                              void* d_out, int out_size)
{
    const float* inp  = (const float*)d_in[0];
    const float* Wi   = (const float*)d_in[1];
    const float* Wf   = (const float*)d_in[2];
    const float* Wc   = (const float*)d_in[3];
    const float* Wo   = (const float*)d_in[4];
    const float* Uig  = (const float*)d_in[5];
    const float* Ufg  = (const float*)d_in[6];
    const float* Ucg  = (const float*)d_in[7];
    const float* Uog  = (const float*)d_in[8];
    const float* Wmem = (const float*)d_in[9];
    const float* Umem = (const float*)d_in[10];
    const float* bi   = (const float*)d_in[11];
    const float* bf   = (const float*)d_in[12];
    const float* bc   = (const float*)d_in[13];
    const float* bo   = (const float*)d_in[14];
    float* out = (float*)d_out;

    cudaFuncSetAttribute(proj_kernel,
                         cudaFuncAttributeMaxDynamicSharedMemorySize,
                         K1_SMEM_BYTES);
    dim3 pg(16, 1024);
    proj_kernel<<<pg, 256, K1_SMEM_BYTES, 0>>>(inp, Wi, Wf, Wc, Wo,
                                               bi, bf, bc, bo);

    cudaFuncSetAttribute(recur_kernel,
                         cudaFuncAttributeMaxDynamicSharedMemorySize,
                         R_SMEM_BYTES);
    recur_kernel<<<128, 640, R_SMEM_BYTES, 0>>>(Uig, Ufg, Ucg, Uog,
                                                Wmem, Umem, out);
}